// round 12
// baseline (speedup 1.0000x reference)
#include <cuda_runtime.h>

// LIF neuron: x is (N*T, F), row b = n*T + t, T=4, N=64, F=65536.
// Per (n,f): v=0; 4x { v = v*0.5 + x_t; s=(v>=1); v-=s; } out=s.
//
// R12: champion body (front-batched ldcs loads, stcs stores, 32-bit
// shift/mask indexing, 1 float4 column/thread) at block=512 instead of 256.
// Same occupancy (30 regs -> 3 CTAs/SM = 48 warps), half the CTA count
// (2048): fewer work-distributor launch/drain events, fuller per-SMSP warp
// slots per CTA. Problem is at the LTS-cap floor (~134MB / ~7.6TB/s =
// ~17.6us kernel); this probes the last launch-geometry micro-axis.

#define T_STEPS 4
#define DECAY 0.5f
#define VTH 1.0f

#define FVEC 16384          // F/4
#define NTHREADS 512
#define BLOCKS_PER_N 32     // FVEC / 512 threads

__global__ void __launch_bounds__(NTHREADS) lif_kernel(const float4* __restrict__ x,
                                                       float4* __restrict__ out)
{
    // blockIdx.x = n * BLOCKS_PER_N + c ; power-of-two split, all 32-bit.
    unsigned n = blockIdx.x >> 5;              // / 32
    unsigned c = blockIdx.x & 31;              // % 32

    unsigned base = n * (T_STEPS * FVEC) + c * (unsigned)NTHREADS + threadIdx.x;

    // Front-batch 4 streaming loads (evict-first; no intra-kernel reuse).
    float4 x0 = __ldcs(&x[base]);
    float4 x1 = __ldcs(&x[base + FVEC]);
    float4 x2 = __ldcs(&x[base + 2 * FVEC]);
    float4 x3 = __ldcs(&x[base + 3 * FVEC]);

    float4 v = make_float4(0.f, 0.f, 0.f, 0.f);
    float4 s0, s1, s2, s3;

#define STEP1(vc, xt, st)                                                  \
    (vc) = (vc) * DECAY + (xt); (st) = ((vc) >= VTH) ? 1.f : 0.f; (vc) -= (st) * VTH;
#define STEP4(xt, st)            \
    STEP1(v.x, (xt).x, (st).x)   \
    STEP1(v.y, (xt).y, (st).y)   \
    STEP1(v.z, (xt).z, (st).z)   \
    STEP1(v.w, (xt).w, (st).w)

    STEP4(x0, s0)
    STEP4(x1, s1)
    STEP4(x2, s2)
    STEP4(x3, s3)
#undef STEP4
#undef STEP1

    __stcs(&out[base],            s0);
    __stcs(&out[base + FVEC],     s1);
    __stcs(&out[base + 2 * FVEC], s2);
    __stcs(&out[base + 3 * FVEC], s3);
}

extern "C" void kernel_launch(void* const* d_in, const int* in_sizes, int n_in,
                              void* d_out, int out_size)
{
    const float* x = (const float*)d_in[0];
    float* out = (float*)d_out;

    const int N = 64;                       // 256 rows / T=4
    int blocks = N * BLOCKS_PER_N;          // 2048 blocks x 512 threads

    lif_kernel<<<blocks, NTHREADS>>>((const float4*)x, (float4*)out);
}